// round 3
// baseline (speedup 1.0000x reference)
#include <cuda_runtime.h>
#include <cstddef>

// ---------------------------------------------------------------------------
// TDNN x-vector forward. Shapes (fixed by the problem):
//  x: [32, 2048, 20] -> transpose -> [B=32, F=20, T0=2048]
//  L1: splice step=1 NOFF=5 (K=100)  -> [B,512,2044]  relu, bn1 (no affine)
//  L2: splice step=2 NOFF=3 (K=1536) -> [B,512,2040]  relu, bn2
//  L3: splice step=3 NOFF=3 (K=1536) -> [B,512,2034]  relu, bn3
//  L4: 512->512 (K=512)              -> [B,512,2034]  relu6, bn4
//  L5: 512->1500 (K=512)             -> [B,1500,2034] relu6, bn5
//  stats pooling (mean + unbiased std over T) -> [B,3000]
//  fc1 3000->512 relu6 bn_c ; fc2 512->512 relu6 bn_c -> out [32,512]
// BNs are folded into the *next* layer's weights (w' = w*a, b' = b + sum w*d).
// ---------------------------------------------------------------------------

#define EPSF 1e-5f

constexpr int BB = 32;
constexpr int F0 = 20;
constexpr int T0 = 2048;
constexpr int C1 = 512;
constexpr int T1 = 2044;
constexpr int T2 = 2040;
constexpr int T3 = 2034;
constexpr int T4 = 2034;
constexpr int C5 = 1500;
constexpr int T5 = 2034;

// ------------------------------- scratch -----------------------------------
__device__ float g_xT[(size_t)BB * F0 * T0];
__device__ float g_a1[(size_t)BB * C1 * T1];
__device__ float g_a2[(size_t)BB * C1 * T2];
__device__ float g_a3[(size_t)BB * C1 * T3];
__device__ float g_a4[(size_t)BB * C1 * T4];
__device__ float g_a5[(size_t)BB * C5 * T5];

__device__ float g_w2p[(size_t)C1 * 1536];
__device__ float g_w3p[(size_t)C1 * 1536];
__device__ float g_w4p[(size_t)C1 * C1];
__device__ float g_w5p[(size_t)C5 * C1];
__device__ float g_b2p[C1], g_b3p[C1], g_b4p[C1], g_b5p[C5];

__device__ float g_mean1[C1], g_istd1[C1];
__device__ float g_mean2[C1], g_istd2[C1];
__device__ float g_mean3[C1], g_istd3[C1];
__device__ float g_mean4[C1], g_istd4[C1];
__device__ float g_mean5[C5], g_istd5[C5];

__device__ float g_rsum[BB * C5], g_rsq[BB * C5];
__device__ float g_pool[BB * 3000];
__device__ float g_z1[BB * 512], g_u1[BB * 512], g_z2[BB * 512];

// ------------------------------ kernels ------------------------------------

__global__ void transpose_x(const float* __restrict__ x, float* __restrict__ xt) {
    int idx = blockIdx.x * blockDim.x + threadIdx.x;
    int total = BB * F0 * T0;
    if (idx >= total) return;
    int t = idx % T0;
    int f = (idx / T0) % F0;
    int b = idx / (T0 * F0);
    xt[idx] = x[((size_t)b * T0 + t) * F0 + f];
}

// Fused splice + conv1x1 (GEMM). out[b,o,t] = act(bias[o] + sum_k w[o,k]*in[b, k/NOFF, t + (k%NOFF)*step])
// 64x64 output tile per block, BK=16, 256 threads, 4x4 per thread. act: 0=relu, 1=relu6
template <int NOFF>
__global__ __launch_bounds__(256)
void gemm_splice(const float* __restrict__ in, int Cin, int Tin,
                 const float* __restrict__ w, const float* __restrict__ bias,
                 float* __restrict__ out, int Cout, int Tout,
                 int K, int step, int act) {
    __shared__ float Ws[16][65];
    __shared__ float Is[16][64];

    int b = blockIdx.z;
    int t0 = blockIdx.x * 64;
    int o0 = blockIdx.y * 64;
    const float* inb = in + (size_t)b * Cin * Tin;

    int tx = threadIdx.x, ty = threadIdx.y;
    int tid = ty * 16 + tx;

    float acc[4][4];
#pragma unroll
    for (int i = 0; i < 4; i++)
#pragma unroll
        for (int j = 0; j < 4; j++) acc[i][j] = 0.f;

    int nk = (K + 15) / 16;
    for (int kt = 0; kt < nk; kt++) {
        int k0 = kt * 16;
        // load weight tile (consecutive threads -> consecutive k : coalesced)
#pragma unroll
        for (int u = 0; u < 4; u++) {
            int l = tid + u * 256;
            int oo = l >> 4, kk = l & 15;
            int o = o0 + oo, k = k0 + kk;
            float v = 0.f;
            if (o < Cout && k < K) v = w[(size_t)o * K + k];
            Ws[kk][oo] = v;
        }
        // load input tile (consecutive threads -> consecutive t : coalesced)
#pragma unroll
        for (int u = 0; u < 4; u++) {
            int l = tid + u * 256;
            int kk = l >> 6, tt = l & 63;
            int k = k0 + kk;
            int t = t0 + tt;
            float v = 0.f;
            if (k < K && t < Tout) {
                int cin = k / NOFF;
                int off = (k - cin * NOFF) * step;
                v = inb[(size_t)cin * Tin + t + off];
            }
            Is[kk][tt] = v;
        }
        __syncthreads();
#pragma unroll
        for (int kk = 0; kk < 16; kk++) {
            float a[4], c[4];
#pragma unroll
            for (int i = 0; i < 4; i++) a[i] = Ws[kk][ty * 4 + i];
#pragma unroll
            for (int j = 0; j < 4; j++) c[j] = Is[kk][tx * 4 + j];
#pragma unroll
            for (int i = 0; i < 4; i++)
#pragma unroll
                for (int j = 0; j < 4; j++) acc[i][j] += a[i] * c[j];
        }
        __syncthreads();
    }

#pragma unroll
    for (int i = 0; i < 4; i++) {
        int o = o0 + ty * 4 + i;
        if (o >= Cout) continue;
        float bv = bias[o];
#pragma unroll
        for (int j = 0; j < 4; j++) {
            int t = t0 + tx * 4 + j;
            if (t >= Tout) continue;
            float v = acc[i][j] + bv;
            v = fmaxf(v, 0.f);
            if (act == 1) v = fminf(v, 6.f);
            out[((size_t)b * Cout + o) * Tout + t] = v;
        }
    }
}

// per-channel mean / inv-std over (batch, time)
__global__ void bn_stats(const float* __restrict__ x, int C, int T,
                         float* __restrict__ mean, float* __restrict__ istd) {
    int c = blockIdx.x;
    float s = 0.f, ss = 0.f;
    for (int b = 0; b < BB; b++) {
        const float* p = x + ((size_t)b * C + c) * T;
        for (int t = threadIdx.x; t < T; t += blockDim.x) {
            float v = p[t];
            s += v;
            ss += v * v;
        }
    }
    __shared__ float sh1[256], sh2[256];
    sh1[threadIdx.x] = s;
    sh2[threadIdx.x] = ss;
    __syncthreads();
    for (int d = 128; d > 0; d >>= 1) {
        if (threadIdx.x < d) {
            sh1[threadIdx.x] += sh1[threadIdx.x + d];
            sh2[threadIdx.x] += sh2[threadIdx.x + d];
        }
        __syncthreads();
    }
    if (threadIdx.x == 0) {
        float N = (float)BB * (float)T;
        float m = sh1[0] / N;
        float var = sh2[0] / N - m * m;
        mean[c] = m;
        istd[c] = rsqrtf(var + EPSF);
    }
}

// fold preceding BN into this layer's weights.
// a[cin] = istd*g, d[cin] = beta - mean*a. wp = w*a[cin(k)], bp = bias + sum_k w*d
__global__ void fold_kernel(const float* __restrict__ w, const float* __restrict__ bias,
                            const float* __restrict__ mean, const float* __restrict__ istd,
                            const float* __restrict__ g, const float* __restrict__ be,
                            float* __restrict__ wp, float* __restrict__ bp,
                            int K, int NOFF) {
    int o = blockIdx.x;
    float part = 0.f;
    for (int k = threadIdx.x; k < K; k += blockDim.x) {
        int cin = k / NOFF;
        float a = istd[cin] * (g ? g[cin] : 1.f);
        float d = (be ? be[cin] : 0.f) - mean[cin] * a;
        float wv = w[(size_t)o * K + k];
        wp[(size_t)o * K + k] = wv * a;
        part += wv * d;
    }
    __shared__ float sh[256];
    sh[threadIdx.x] = part;
    __syncthreads();
    for (int d2 = 128; d2 > 0; d2 >>= 1) {
        if (threadIdx.x < d2) sh[threadIdx.x] += sh[threadIdx.x + d2];
        __syncthreads();
    }
    if (threadIdx.x == 0) bp[o] = bias[o] + sh[0];
}

// per-(b,c) sum & sumsq over time (for stats pooling + bn5 stats)
__global__ void rowstats(const float* __restrict__ x, int C, int T,
                         float* __restrict__ rsum, float* __restrict__ rsq) {
    int c = blockIdx.x;
    int b = blockIdx.y;
    const float* p = x + ((size_t)b * C + c) * T;
    float s = 0.f, ss = 0.f;
    for (int t = threadIdx.x; t < T; t += blockDim.x) {
        float v = p[t];
        s += v;
        ss += v * v;
    }
    __shared__ float sh1[256], sh2[256];
    sh1[threadIdx.x] = s;
    sh2[threadIdx.x] = ss;
    __syncthreads();
    for (int d = 128; d > 0; d >>= 1) {
        if (threadIdx.x < d) {
            sh1[threadIdx.x] += sh1[threadIdx.x + d];
            sh2[threadIdx.x] += sh2[threadIdx.x + d];
        }
        __syncthreads();
    }
    if (threadIdx.x == 0) {
        rsum[b * C + c] = sh1[0];
        rsq[b * C + c] = sh2[0];
    }
}

// bn5 global channel stats from the per-(b,c) row stats
__global__ void chstats5(const float* __restrict__ rsum, const float* __restrict__ rsq,
                         float* __restrict__ mean, float* __restrict__ istd) {
    int c = blockIdx.x * blockDim.x + threadIdx.x;
    if (c >= C5) return;
    float s = 0.f, ss = 0.f;
    for (int b = 0; b < BB; b++) {
        s += rsum[b * C5 + c];
        ss += rsq[b * C5 + c];
    }
    float N = (float)BB * (float)T5;
    float m = s / N;
    float var = ss / N - m * m;
    mean[c] = m;
    istd[c] = rsqrtf(var + EPSF);
}

// stats pooling with bn5 folded in: mean' = a*mean_t + d ; std' = |a|*std_t (unbiased)
__global__ void pool_kernel(const float* __restrict__ rsum, const float* __restrict__ rsq,
                            const float* __restrict__ mean5, const float* __restrict__ istd5,
                            const float* __restrict__ g5, const float* __restrict__ be5,
                            float* __restrict__ pooled) {
    int idx = blockIdx.x * blockDim.x + threadIdx.x;
    if (idx >= BB * C5) return;
    int c = idx % C5;
    int b = idx / C5;
    float Tf = (float)T5;
    float mt = rsum[b * C5 + c] / Tf;
    float vart = (rsq[b * C5 + c] - Tf * mt * mt) / (Tf - 1.f);
    float a = istd5[c] * g5[c];
    float d = be5[c] - mean5[c] * a;
    pooled[(size_t)b * 3000 + c] = a * mt + d;
    pooled[(size_t)b * 3000 + 1500 + c] = fabsf(a) * sqrtf(fmaxf(vart, 0.f));
}

// small FC: out[b,o] = relu6(bias + dot(w[o,:], in[b,:]))
__global__ void fc_kernel(const float* __restrict__ in, const float* __restrict__ w,
                          const float* __restrict__ bias, float* __restrict__ out,
                          int K, int Cout) {
    int o = blockIdx.x, b = blockIdx.y;
    const float* ir = in + (size_t)b * K;
    const float* wr = w + (size_t)o * K;
    float s = 0.f;
    for (int k = threadIdx.x; k < K; k += blockDim.x) s += ir[k] * wr[k];
    __shared__ float sh[128];
    sh[threadIdx.x] = s;
    __syncthreads();
    for (int d = 64; d > 0; d >>= 1) {
        if (threadIdx.x < d) sh[threadIdx.x] += sh[threadIdx.x + d];
        __syncthreads();
    }
    if (threadIdx.x == 0) {
        float v = sh[0] + bias[o];
        v = fminf(fmaxf(v, 0.f), 6.f);
        out[(size_t)b * Cout + o] = v;
    }
}

// BatchNorm over the batch dim for [B, C] (B=32)
__global__ void bnc_kernel(const float* __restrict__ z, const float* __restrict__ g,
                           const float* __restrict__ be, float* __restrict__ out, int C) {
    int c = threadIdx.x + blockIdx.x * blockDim.x;
    if (c >= C) return;
    float s = 0.f, ss = 0.f;
    for (int b = 0; b < BB; b++) {
        float v = z[(size_t)b * C + c];
        s += v;
        ss += v * v;
    }
    float m = s / (float)BB;
    float var = ss / (float)BB - m * m;
    float is = rsqrtf(var + EPSF);
    for (int b = 0; b < BB; b++) {
        out[(size_t)b * C + c] = (z[(size_t)b * C + c] - m) * is * g[c] + be[c];
    }
}

// ------------------------------- host --------------------------------------

static float* symaddr(const void* sym) {
    void* p = nullptr;
    cudaGetSymbolAddress(&p, sym);
    return (float*)p;
}

extern "C" void kernel_launch(void* const* d_in, const int* in_sizes, int n_in,
                              void* d_out, int out_size) {
    const float* x    = (const float*)d_in[0];
    const float* h1w  = (const float*)d_in[1];
    const float* h1b  = (const float*)d_in[2];
    const float* h2w  = (const float*)d_in[3];
    const float* h2b  = (const float*)d_in[4];
    const float* bn2g = (const float*)d_in[5];
    const float* bn2b = (const float*)d_in[6];
    const float* h3w  = (const float*)d_in[7];
    const float* h3b  = (const float*)d_in[8];
    const float* bn3g = (const float*)d_in[9];
    const float* bn3b = (const float*)d_in[10];
    const float* h4w  = (const float*)d_in[11];
    const float* h4b  = (const float*)d_in[12];
    const float* bn4g = (const float*)d_in[13];
    const float* bn4b = (const float*)d_in[14];
    const float* h5w  = (const float*)d_in[15];
    const float* h5b  = (const float*)d_in[16];
    const float* bn5g = (const float*)d_in[17];
    const float* bn5b = (const float*)d_in[18];
    const float* l1w  = (const float*)d_in[19];
    const float* l1b  = (const float*)d_in[20];
    const float* bn6g = (const float*)d_in[21];
    const float* bn6b = (const float*)d_in[22];
    const float* l2w  = (const float*)d_in[23];
    const float* l2b  = (const float*)d_in[24];
    const float* bn7g = (const float*)d_in[25];
    const float* bn7b = (const float*)d_in[26];

    float* xT  = symaddr(g_xT);
    float* a1  = symaddr(g_a1);
    float* a2  = symaddr(g_a2);
    float* a3  = symaddr(g_a3);
    float* a4  = symaddr(g_a4);
    float* a5  = symaddr(g_a5);
    float* w2p = symaddr(g_w2p);
    float* w3p = symaddr(g_w3p);
    float* w4p = symaddr(g_w4p);
    float* w5p = symaddr(g_w5p);
    float* b2p = symaddr(g_b2p);
    float* b3p = symaddr(g_b3p);
    float* b4p = symaddr(g_b4p);
    float* b5p = symaddr(g_b5p);
    float* m1 = symaddr(g_mean1); float* i1 = symaddr(g_istd1);
    float* m2 = symaddr(g_mean2); float* i2 = symaddr(g_istd2);
    float* m3 = symaddr(g_mean3); float* i3 = symaddr(g_istd3);
    float* m4 = symaddr(g_mean4); float* i4 = symaddr(g_istd4);
    float* m5 = symaddr(g_mean5); float* i5 = symaddr(g_istd5);
    float* rsum = symaddr(g_rsum);
    float* rsq  = symaddr(g_rsq);
    float* pool = symaddr(g_pool);
    float* z1 = symaddr(g_z1);
    float* u1 = symaddr(g_u1);
    float* z2 = symaddr(g_z2);

    dim3 thr(16, 16);

    // transpose x -> [B, F, T]
    {
        int total = BB * F0 * T0;
        transpose_x<<<(total + 255) / 256, 256>>>(x, xT);
    }

    // L1: splice(0..4) + conv 100->512, relu
    gemm_splice<5><<<dim3((T1 + 63) / 64, (C1 + 63) / 64, BB), thr>>>(
        xT, F0, T0, h1w, h1b, a1, C1, T1, 100, 1, 0);
    bn_stats<<<C1, 256>>>(a1, C1, T1, m1, i1);

    // L2: fold bn1 (no affine), splice(0,2,4) 1536->512, relu
    fold_kernel<<<C1, 256>>>(h2w, h2b, m1, i1, nullptr, nullptr, w2p, b2p, 1536, 3);
    gemm_splice<3><<<dim3((T2 + 63) / 64, (C1 + 63) / 64, BB), thr>>>(
        a1, C1, T1, w2p, b2p, a2, C1, T2, 1536, 2, 0);
    bn_stats<<<C1, 256>>>(a2, C1, T2, m2, i2);

    // L3: fold bn2, splice(0,3,6) 1536->512, relu
    fold_kernel<<<C1, 256>>>(h3w, h3b, m2, i2, bn2g, bn2b, w3p, b3p, 1536, 3);
    gemm_splice<3><<<dim3((T3 + 63) / 64, (C1 + 63) / 64, BB), thr>>>(
        a2, C1, T2, w3p, b3p, a3, C1, T3, 1536, 3, 0);
    bn_stats<<<C1, 256>>>(a3, C1, T3, m3, i3);

    // L4: fold bn3, 512->512, relu6
    fold_kernel<<<C1, 256>>>(h4w, h4b, m3, i3, bn3g, bn3b, w4p, b4p, 512, 1);
    gemm_splice<1><<<dim3((T4 + 63) / 64, (C1 + 63) / 64, BB), thr>>>(
        a3, C1, T3, w4p, b4p, a4, C1, T4, 512, 0, 1);
    bn_stats<<<C1, 256>>>(a4, C1, T4, m4, i4);

    // L5: fold bn4, 512->1500, relu6
    fold_kernel<<<C5, 256>>>(h5w, h5b, m4, i4, bn4g, bn4b, w5p, b5p, 512, 1);
    gemm_splice<1><<<dim3((T5 + 63) / 64, (C5 + 63) / 64, BB), thr>>>(
        a4, C1, T4, w5p, b5p, a5, C5, T5, 512, 0, 1);

    // stats pooling with bn5 folded in
    rowstats<<<dim3(C5, BB), 256>>>(a5, C5, T5, rsum, rsq);
    chstats5<<<(C5 + 255) / 256, 256>>>(rsum, rsq, m5, i5);
    pool_kernel<<<(BB * C5 + 255) / 256, 256>>>(rsum, rsq, m5, i5, bn5g, bn5b, pool);

    // fc1 + bn6
    fc_kernel<<<dim3(512, BB), 128>>>(pool, l1w, l1b, z1, 3000, 512);
    bnc_kernel<<<2, 256>>>(z1, bn6g, bn6b, u1, 512);

    // fc2 + bn7 -> output
    fc_kernel<<<dim3(512, BB), 128>>>(u1, l2w, l2b, z2, 512, 512);
    bnc_kernel<<<2, 256>>>(z2, bn7g, bn7b, (float*)d_out, 512);
}

// round 5
// speedup vs baseline: 2.2065x; 2.2065x over previous
#include <cuda_runtime.h>
#include <cuda_fp16.h>
#include <cstdint>
#include <cstddef>

#define EPSF 1e-5f
constexpr int BB = 32, F0 = 20, T0 = 2048;
constexpr int T1 = 2044, T2 = 2040, T3 = 2034, T5 = 2034;
constexpr int C5 = 1500, C5P = 1536, NS = 256;

// ------------------------------- scratch -----------------------------------
__device__ __align__(16) __half g_xhi[(size_t)BB * T0 * 32],  g_xlo[(size_t)BB * T0 * 32];
__device__ __align__(16) __half g_a1hi[(size_t)BB * T1 * 512], g_a1lo[(size_t)BB * T1 * 512];
__device__ __align__(16) __half g_a2hi[(size_t)BB * T2 * 512], g_a2lo[(size_t)BB * T2 * 512];
__device__ __align__(16) __half g_a3hi[(size_t)BB * T3 * 512], g_a3lo[(size_t)BB * T3 * 512];
__device__ __align__(16) __half g_a4hi[(size_t)BB * T3 * 512], g_a4lo[(size_t)BB * T3 * 512];
__device__ float g_a5[(size_t)BB * T5 * C5P];
__device__ __align__(16) __half g_w1hi[512 * 160],  g_w1lo[512 * 160];
__device__ __align__(16) __half g_w2hi[512 * 1536], g_w2lo[512 * 1536];
__device__ __align__(16) __half g_w3hi[512 * 1536], g_w3lo[512 * 1536];
__device__ __align__(16) __half g_w4hi[512 * 512],  g_w4lo[512 * 512];
__device__ __align__(16) __half g_w5hi[C5P * 512],  g_w5lo[C5P * 512];
__device__ float g_b1p[512], g_b2p[512], g_b3p[512], g_b4p[512], g_b5p[C5P];
__device__ float g_ps[NS * 512], g_pq[NS * 512];
__device__ float g_m1[512], g_i1[512], g_m2[512], g_i2[512];
__device__ float g_m3[512], g_i3[512], g_m4[512], g_i4[512];
__device__ float g_m5[C5], g_i5[C5];
__device__ float g_rsum[BB * C5], g_rsq[BB * C5];
__device__ float g_pool[BB * 3000];
__device__ float g_z1[BB * 512], g_u1[BB * 512], g_z2[BB * 512];

// ----------------------------- helpers --------------------------------------
__device__ __forceinline__ uint32_t s2u(const void* p) {
    uint32_t a;
    asm("{ .reg .u64 t; cvta.to.shared.u64 t, %1; cvt.u32.u64 %0, t; }" : "=r"(a) : "l"(p));
    return a;
}
__device__ __forceinline__ void ldm_x4(uint32_t a[4], uint32_t addr) {
    asm volatile("ldmatrix.sync.aligned.m8n8.x4.shared.b16 {%0,%1,%2,%3}, [%4];"
                 : "=r"(a[0]), "=r"(a[1]), "=r"(a[2]), "=r"(a[3]) : "r"(addr));
}
__device__ __forceinline__ void ldm_x2(uint32_t b[2], uint32_t addr) {
    asm volatile("ldmatrix.sync.aligned.m8n8.x2.shared.b16 {%0,%1}, [%2];"
                 : "=r"(b[0]), "=r"(b[1]) : "r"(addr));
}
__device__ __forceinline__ void mma16816(float c[4], const uint32_t a[4], const uint32_t b[2]) {
    asm volatile("mma.sync.aligned.m16n8k16.row.col.f32.f16.f16.f32 "
                 "{%0,%1,%2,%3}, {%4,%5,%6,%7}, {%8,%9}, {%0,%1,%2,%3};"
                 : "+f"(c[0]), "+f"(c[1]), "+f"(c[2]), "+f"(c[3])
                 : "r"(a[0]), "r"(a[1]), "r"(a[2]), "r"(a[3]), "r"(b[0]), "r"(b[1]));
}
__device__ __forceinline__ void cpa16(uint32_t dst, const void* src, int sz) {
    asm volatile("cp.async.ca.shared.global [%0], [%1], 16, %2;" :: "r"(dst), "l"(src), "r"(sz));
}
#define CP_COMMIT() asm volatile("cp.async.commit_group;" ::: "memory")
#define CP_WAIT1() asm volatile("cp.async.wait_group 1;" ::: "memory")
#define CP_WAIT0() asm volatile("cp.async.wait_group 0;" ::: "memory")

// ------------------------------ prep kernels --------------------------------
__global__ void xsplit(const float* __restrict__ x, __half* __restrict__ xh, __half* __restrict__ xl) {
    int idx = blockIdx.x * 256 + threadIdx.x;
    if (idx >= BB * T0 * 32) return;
    int f = idx & 31, bt = idx >> 5;
    float v = (f < F0) ? x[(size_t)bt * F0 + f] : 0.f;
    __half h = __float2half(v);
    xh[idx] = h;
    xl[idx] = __float2half(v - __half2float(h));
}

// fold prev BN into weights, reorder k'=j*Cpad+c, fp16 hi/lo split
__global__ void fold_split(const float* __restrict__ w, const float* __restrict__ bias,
                           const float* __restrict__ mean, const float* __restrict__ istd,
                           const float* __restrict__ g, const float* __restrict__ be,
                           __half* __restrict__ wh, __half* __restrict__ wl, float* __restrict__ bp,
                           int Korig, int NOFF, int C, int Cpad, int Cout, int Kp) {
    int o = blockIdx.x;
    float part = 0.f;
    for (int k = threadIdx.x; k < Kp; k += 256) {
        int j = k / Cpad, c = k - j * Cpad;
        float wa = 0.f;
        if (o < Cout && c < C) {
            float a = 1.f, d = 0.f;
            if (mean) { a = istd[c] * (g ? g[c] : 1.f); d = (be ? be[c] : 0.f) - mean[c] * a; }
            float wv = w[(size_t)o * Korig + c * NOFF + j];
            wa = wv * a;
            part += wv * d;
        }
        __half h = __float2half(wa);
        wh[(size_t)o * Kp + k] = h;
        wl[(size_t)o * Kp + k] = __float2half(wa - __half2float(h));
    }
    __shared__ float sh[256];
    sh[threadIdx.x] = part;
    __syncthreads();
    for (int d2 = 128; d2 > 0; d2 >>= 1) {
        if (threadIdx.x < d2) sh[threadIdx.x] += sh[threadIdx.x + d2];
        __syncthreads();
    }
    if (threadIdx.x == 0) bp[o] = (o < Cout ? bias[o] : 0.f) + sh[0];
}

// -------------------------- mma.sync GEMM -----------------------------------
// out[b][t][o] = act(bias[o] + sum_k' A(b, t+(k'/Cpad)*step, k'%Cpad) * W(o,k'))
// CTA tile 128x128, BK=32, 8 warps (4m x 2n), warp tile 32x64. fp16 hi/lo 3-term.
// smem stage = 4 tiles x (128 rows x 80B) = 40960B, double-buffered.
__global__ __launch_bounds__(256)
void mma_gemm(const __half* __restrict__ Ah, const __half* __restrict__ Al,
              const __half* __restrict__ Wh, const __half* __restrict__ Wl,
              const float* __restrict__ bias,
              __half* __restrict__ Oh, __half* __restrict__ Ol, float* __restrict__ Of,
              int Tin, int Tout, int Cpad, int step, int Kp, int Coutp, int act) {
    extern __shared__ char smem[];
    uint32_t su = s2u(smem);
    int tid = threadIdx.x, lane = tid & 31, wid = tid >> 5;
    int b = blockIdx.z, t0 = blockIdx.x * 128, obase = blockIdx.y * 128;
    int wm = wid >> 1, wn = wid & 1;
    int nk = Kp >> 5;

    float acc[2][8][4];
#pragma unroll
    for (int i = 0; i < 2; i++)
#pragma unroll
        for (int j = 0; j < 8; j++)
#pragma unroll
            for (int q = 0; q < 4; q++) acc[i][j][q] = 0.f;

    auto load_stage = [&](int buf, int kc) {
        int kc0 = kc << 5;
        int j = kc0 / Cpad, c0 = kc0 - j * Cpad, off = j * step;
        uint32_t sb = su + buf * 40960;
        const __half* pa[2] = {Ah, Al};
        const __half* pw[2] = {Wh, Wl};
#pragma unroll
        for (int h = 0; h < 2; h++) {
#pragma unroll
            for (int i = 0; i < 2; i++) {
                int e = tid + i * 256, r = e >> 2, c = e & 3;
                cpa16(sb + h * 10240 + r * 80 + c * 16,
                      pa[h] + ((size_t)b * Tin + t0 + off + r) * Cpad + c0 + c * 8,
                      (t0 + r < Tout) ? 16 : 0);
            }
#pragma unroll
            for (int i = 0; i < 2; i++) {
                int e = tid + i * 256, r = e >> 2, c = e & 3;
                cpa16(sb + 20480 + h * 10240 + r * 80 + c * 16,
                      pw[h] + ((size_t)(obase + r)) * Kp + kc0 + c * 8, 16);
            }
        }
        CP_COMMIT();
    };

    auto compute = [&](int buf) {
        uint32_t sb = su + buf * 40960;
#pragma unroll
        for (int ks = 0; ks < 2; ks++) {
            uint32_t ah[2][4], al[2][4];
#pragma unroll
            for (int mf = 0; mf < 2; mf++) {
                int row = wm * 32 + mf * 16 + (lane & 15);
                uint32_t addr = sb + row * 80 + (ks * 16 + ((lane >> 4) << 3)) * 2;
                ldm_x4(ah[mf], addr);
                ldm_x4(al[mf], addr + 10240);
            }
#pragma unroll
            for (int nb = 0; nb < 2; nb++) {
                uint32_t bh[4][2], bl[4][2];
#pragma unroll
                for (int q = 0; q < 4; q++) {
                    int l16 = lane & 15;
                    int rowb = wn * 64 + (nb * 4 + q) * 8 + (l16 & 7);
                    uint32_t addr = sb + 20480 + rowb * 80 + (ks * 16 + ((l16 >> 3) << 3)) * 2;
                    ldm_x2(bh[q], addr);
                    ldm_x2(bl[q], addr + 10240);
                }
#pragma unroll
                for (int mf = 0; mf < 2; mf++)
#pragma unroll
                    for (int q = 0; q < 4; q++) {
                        int nf = nb * 4 + q;
                        mma16816(acc[mf][nf], ah[mf], bh[q]);
                        mma16816(acc[mf][nf], ah[mf], bl[q]);
                        mma16816(acc[mf][nf], al[mf], bh[q]);
                    }
            }
        }
    };

    load_stage(0, 0);
    load_stage(1, 1);
    for (int kc = 0; kc < nk; kc++) {
        if (kc < nk - 2) CP_WAIT1(); else CP_WAIT0();
        __syncthreads();
        compute(kc & 1);
        __syncthreads();
        if (kc + 2 < nk) load_stage(kc & 1, kc + 2);
    }

    // epilogue
    int l4 = lane >> 2, l2 = (lane & 3) << 1;
#pragma unroll
    for (int mf = 0; mf < 2; mf++)
#pragma unroll
        for (int hh = 0; hh < 2; hh++) {
            int t = t0 + wm * 32 + mf * 16 + l4 + hh * 8;
            if (t >= Tout) continue;
            size_t ro = ((size_t)b * Tout + t) * Coutp + obase + wn * 64;
#pragma unroll
            for (int nf = 0; nf < 8; nf++) {
                int o = nf * 8 + l2;
                float v0 = acc[mf][nf][hh * 2 + 0] + bias[obase + wn * 64 + o];
                float v1 = acc[mf][nf][hh * 2 + 1] + bias[obase + wn * 64 + o + 1];
                v0 = fmaxf(v0, 0.f); v1 = fmaxf(v1, 0.f);
                if (act) { v0 = fminf(v0, 6.f); v1 = fminf(v1, 6.f); }
                if (Of) {
                    *(float2*)(Of + ro + o) = make_float2(v0, v1);
                } else {
                    __half h0 = __float2half(v0), h1 = __float2half(v1);
                    *(__half2*)(Oh + ro + o) = __halves2half2(h0, h1);
                    *(__half2*)(Ol + ro + o) = __halves2half2(
                        __float2half(v0 - __half2float(h0)), __float2half(v1 - __half2float(h1)));
                }
            }
        }
}

// --------------------------- stats / tail -----------------------------------
__global__ void statpart(const __half* __restrict__ hi, const __half* __restrict__ lo,
                         float* __restrict__ ps, float* __restrict__ pq, int Mrows, int Cpad) {
    int c = blockIdx.x * 256 + threadIdx.x;
    int s = blockIdx.y, ns = gridDim.y;
    int per = (Mrows + ns - 1) / ns;
    int m0 = s * per, m1 = min(m0 + per, Mrows);
    float sa = 0.f, sq = 0.f;
    for (int m = m0; m < m1; m++) {
        float v = __half2float(hi[(size_t)m * Cpad + c]) + __half2float(lo[(size_t)m * Cpad + c]);
        sa += v; sq += v * v;
    }
    ps[(size_t)s * Cpad + c] = sa;
    pq[(size_t)s * Cpad + c] = sq;
}
__global__ void statfin(const float* __restrict__ ps, const float* __restrict__ pq,
                        float* __restrict__ mean, float* __restrict__ istd, int Cpad, float N) {
    int c = blockIdx.x * 256 + threadIdx.x;
    if (c >= Cpad) return;
    float s = 0.f, q = 0.f;
    for (int i = 0; i < NS; i++) { s += ps[(size_t)i * Cpad + c]; q += pq[(size_t)i * Cpad + c]; }
    float m = s / N;
    mean[c] = m;
    istd[c] = rsqrtf(q / N - m * m + EPSF);
}
__global__ void rowstats_tc(const float* __restrict__ a5, float* __restrict__ rsum, float* __restrict__ rsq) {
    int c = blockIdx.x * 256 + threadIdx.x;
    int b = blockIdx.y;
    if (c >= C5) return;
    const float* base = a5 + (size_t)b * T5 * C5P + c;
    float s = 0.f, q = 0.f;
    for (int t = 0; t < T5; t++) { float v = base[(size_t)t * C5P]; s += v; q += v * v; }
    rsum[b * C5 + c] = s;
    rsq[b * C5 + c] = q;
}
__global__ void chstats5(const float* __restrict__ rsum, const float* __restrict__ rsq,
                         float* __restrict__ mean, float* __restrict__ istd) {
    int c = blockIdx.x * 256 + threadIdx.x;
    if (c >= C5) return;
    float s = 0.f, ss = 0.f;
    for (int b = 0; b < BB; b++) { s += rsum[b * C5 + c]; ss += rsq[b * C5 + c]; }
    float N = (float)BB * (float)T5;
    float m = s / N;
    mean[c] = m;
    istd[c] = rsqrtf(ss / N - m * m + EPSF);
}
__global__ void pool_kernel(const float* __restrict__ rsum, const float* __restrict__ rsq,
                            const float* __restrict__ m5, const float* __restrict__ i5,
                            const float* __restrict__ g5, const float* __restrict__ be5,
                            float* __restrict__ pooled) {
    int idx = blockIdx.x * 256 + threadIdx.x;
    if (idx >= BB * C5) return;
    int c = idx % C5, b = idx / C5;
    float Tf = (float)T5;
    float mt = rsum[b * C5 + c] / Tf;
    float vart = (rsq[b * C5 + c] - Tf * mt * mt) / (Tf - 1.f);
    float a = i5[c] * g5[c];
    float d = be5[c] - m5[c] * a;
    pooled[(size_t)b * 3000 + c] = a * mt + d;
    pooled[(size_t)b * 3000 + 1500 + c] = fabsf(a) * sqrtf(fmaxf(vart, 0.f));
}
__global__ void fc_kernel(const float* __restrict__ in, const float* __restrict__ w,
                          const float* __restrict__ bias, float* __restrict__ out, int K, int Cout) {
    int o = blockIdx.x, b = blockIdx.y;
    const float* ir = in + (size_t)b * K;
    const float* wr = w + (size_t)o * K;
    float s = 0.f;
    for (int k = threadIdx.x; k < K; k += 128) s += ir[k] * wr[k];
    __shared__ float sh[128];
    sh[threadIdx.x] = s;
    __syncthreads();
    for (int d = 64; d > 0; d >>= 1) {
        if (threadIdx.x < d) sh[threadIdx.x] += sh[threadIdx.x + d];
        __syncthreads();
    }
    if (threadIdx.x == 0) out[(size_t)b * Cout + o] = fminf(fmaxf(sh[0] + bias[o], 0.f), 6.f);
}
__global__ void bnc_kernel(const float* __restrict__ z, const float* __restrict__ g,
                           const float* __restrict__ be, float* __restrict__ out, int C) {
    int c = threadIdx.x + blockIdx.x * 256;
    if (c >= C) return;
    float s = 0.f, ss = 0.f;
    for (int b = 0; b < BB; b++) { float v = z[(size_t)b * C + c]; s += v; ss += v * v; }
    float m = s / (float)BB;
    float is = rsqrtf(ss / (float)BB - m * m + EPSF);
    for (int b = 0; b < BB; b++)
        out[(size_t)b * C + c] = (z[(size_t)b * C + c] - m) * is * g[c] + be[c];
}

// ------------------------------- host ---------------------------------------
static void* sa(const void* sym) { void* p = nullptr; cudaGetSymbolAddress(&p, sym); return p; }

extern "C" void kernel_launch(void* const* d_in, const int* in_sizes, int n_in,
                              void* d_out, int out_size) {
    const float* x = (const float*)d_in[0];
    const float *h1w = (const float*)d_in[1], *h1b = (const float*)d_in[2];
    const float *h2w = (const float*)d_in[3], *h2b = (const float*)d_in[4];
    const float *bn2g = (const float*)d_in[5], *bn2b = (const float*)d_in[6];
    const float *h3w = (const float*)d_in[7], *h3b = (const float*)d_in[8];
    const float *bn3g = (const float*)d_in[9], *bn3b = (const float*)d_in[10];
    const float *h4w = (const float*)d_in[11], *h4b = (const float*)d_in[12];
    const float *bn4g = (const float*)d_in[13], *bn4b = (const float*)d_in[14];
    const float *h5w = (const float*)d_in[15], *h5b = (const float*)d_in[16];
    const float *bn5g = (const float*)d_in[17], *bn5b = (const float*)d_in[18];
    const float *l1w = (const float*)d_in[19], *l1b = (const float*)d_in[20];
    const float *bn6g = (const float*)d_in[21], *bn6b = (const float*)d_in[22];
    const float *l2w = (const float*)d_in[23], *l2b = (const float*)d_in[24];
    const float *bn7g = (const float*)d_in[25], *bn7b = (const float*)d_in[26];

    __half *xh = (__half*)sa(g_xhi), *xl = (__half*)sa(g_xlo);
    __half *a1h = (__half*)sa(g_a1hi), *a1l = (__half*)sa(g_a1lo);
    __half *a2h = (__half*)sa(g_a2hi), *a2l = (__half*)sa(g_a2lo);
    __half *a3h = (__half*)sa(g_a3hi), *a3l = (__half*)sa(g_a3lo);
    __half *a4h = (__half*)sa(g_a4hi), *a4l = (__half*)sa(g_a4lo);
    float *a5 = (float*)sa(g_a5);
    __half *w1h = (__half*)sa(g_w1hi), *w1l = (__half*)sa(g_w1lo);
    __half *w2h = (__half*)sa(g_w2hi), *w2l = (__half*)sa(g_w2lo);
    __half *w3h = (__half*)sa(g_w3hi), *w3l = (__half*)sa(g_w3lo);
    __half *w4h = (__half*)sa(g_w4hi), *w4l = (__half*)sa(g_w4lo);
    __half *w5h = (__half*)sa(g_w5hi), *w5l = (__half*)sa(g_w5lo);
    float *b1 = (float*)sa(g_b1p), *b2 = (float*)sa(g_b2p), *b3 = (float*)sa(g_b3p);
    float *b4 = (float*)sa(g_b4p), *b5 = (float*)sa(g_b5p);
    float *ps = (float*)sa(g_ps), *pq = (float*)sa(g_pq);
    float *m1 = (float*)sa(g_m1), *i1 = (float*)sa(g_i1), *m2 = (float*)sa(g_m2), *i2 = (float*)sa(g_i2);
    float *m3 = (float*)sa(g_m3), *i3 = (float*)sa(g_i3), *m4 = (float*)sa(g_m4), *i4 = (float*)sa(g_i4);
    float *m5 = (float*)sa(g_m5), *i5 = (float*)sa(g_i5);
    float *rsum = (float*)sa(g_rsum), *rsq = (float*)sa(g_rsq), *pool = (float*)sa(g_pool);
    float *z1 = (float*)sa(g_z1), *u1 = (float*)sa(g_u1), *z2 = (float*)sa(g_z2);

    const int SMEMB = 2 * 40960;
    cudaFuncSetAttribute(mma_gemm, cudaFuncAttributeMaxDynamicSharedMemorySize, SMEMB);

    xsplit<<<(BB * T0 * 32 + 255) / 256, 256>>>(x, xh, xl);

    // L1: K'=160 (5 offset blocks of Cpad=32), step 1, relu
    fold_split<<<512, 256>>>(h1w, h1b, nullptr, nullptr, nullptr, nullptr, w1h, w1l, b1, 100, 5, 20, 32, 512, 160);
    mma_gemm<<<dim3(16, 4, BB), 256, SMEMB>>>(xh, xl, w1h, w1l, b1, a1h, a1l, nullptr, T0, T1, 32, 1, 160, 512, 0);
    statpart<<<dim3(2, NS), 256>>>(a1h, a1l, ps, pq, BB * T1, 512);
    statfin<<<2, 256>>>(ps, pq, m1, i1, 512, (float)BB * (float)T1);

    // L2: fold bn1, offsets {0,2,4}, relu
    fold_split<<<512, 256>>>(h2w, h2b, m1, i1, nullptr, nullptr, w2h, w2l, b2, 1536, 3, 512, 512, 512, 1536);
    mma_gemm<<<dim3(16, 4, BB), 256, SMEMB>>>(a1h, a1l, w2h, w2l, b2, a2h, a2l, nullptr, T1, T2, 512, 2, 1536, 512, 0);
    statpart<<<dim3(2, NS), 256>>>(a2h, a2l, ps, pq, BB * T2, 512);
    statfin<<<2, 256>>>(ps, pq, m2, i2, 512, (float)BB * (float)T2);

    // L3: fold bn2, offsets {0,3,6}, relu
    fold_split<<<512, 256>>>(h3w, h3b, m2, i2, bn2g, bn2b, w3h, w3l, b3, 1536, 3, 512, 512, 512, 1536);
    mma_gemm<<<dim3(16, 4, BB), 256, SMEMB>>>(a2h, a2l, w3h, w3l, b3, a3h, a3l, nullptr, T2, T3, 512, 3, 1536, 512, 0);
    statpart<<<dim3(2, NS), 256>>>(a3h, a3l, ps, pq, BB * T3, 512);
    statfin<<<2, 256>>>(ps, pq, m3, i3, 512, (float)BB * (float)T3);

    // L4: fold bn3, 512->512, relu6
    fold_split<<<512, 256>>>(h4w, h4b, m3, i3, bn3g, bn3b, w4h, w4l, b4, 512, 1, 512, 512, 512, 512);
    mma_gemm<<<dim3(16, 4, BB), 256, SMEMB>>>(a3h, a3l, w4h, w4l, b4, a4h, a4l, nullptr, T3, T3, 512, 0, 512, 512, 1);
    statpart<<<dim3(2, NS), 256>>>(a4h, a4l, ps, pq, BB * T3, 512);
    statfin<<<2, 256>>>(ps, pq, m4, i4, 512, (float)BB * (float)T3);

    // L5: fold bn4, 512->1500 (pad 1536), relu6 -> fp32 a5
    fold_split<<<C5P, 256>>>(h5w, h5b, m4, i4, bn4g, bn4b, w5h, w5l, b5, 512, 1, 512, 512, C5, 512);
    mma_gemm<<<dim3(16, 12, BB), 256, SMEMB>>>(a4h, a4l, w5h, w5l, b5, nullptr, nullptr, a5, T3, T5, 512, 0, 512, C5P, 1);

    // stats pooling (bn5 folded analytically)
    rowstats_tc<<<dim3(6, BB), 256>>>(a5, rsum, rsq);
    chstats5<<<6, 256>>>(rsum, rsq, m5, i5);
    pool_kernel<<<(BB * C5 + 255) / 256, 256>>>(rsum, rsq, m5, i5, bn5g, bn5b, pool);

    // tail FCs
    fc_kernel<<<dim3(512, BB), 128>>>(pool, l1w, l1b, z1, 3000, 512);
    bnc_kernel<<<2, 256>>>(z1, bn6g, bn6b, u1, 512);
    fc_kernel<<<dim3(512, BB), 128>>>(u1, l2w, l2b, z2, 512, 512);
    bnc_kernel<<<2, 256>>>(z2, bn7g, bn7b, (float*)d_out, 512);
}